// round 4
// baseline (speedup 1.0000x reference)
#include <cuda_runtime.h>
#include <cuda_bf16.h>

#define NN 10000      // num nodes (dataset-fixed)
#define EE 640000     // num edges
#define DD 128        // feature dim
#define NSPLIT 8      // atomic contention split factor

// ---- scratch (__device__ globals; no cudaMalloc allowed) -------------------
__device__ int   g_degcnt[NSPLIT][NN];   // out-degree counts (over row), phase-split
__device__ int   g_colcnt[NSPLIT][NN];   // in-degree counts (over col), phase-split
__device__ int   g_off[NN + 1];          // CSR offsets by col
__device__ int   g_cursor[NSPLIT][NN];   // scatter cursors, phase-split
__device__ int   g_srow[EE];             // row[] sorted by col
__device__ float g_dis[NN];              // (deg+1)^{-1/2}
__device__ float g_msg[NN * DD];         // (x@W) * dis[row], fp32

// ---------------------------------------------------------------------------
// K1: zero histograms
// ---------------------------------------------------------------------------
__global__ void k_zero(int n) {
    int i = blockIdx.x * blockDim.x + threadIdx.x;
    if (i < n) {
#pragma unroll
        for (int q = 0; q < NSPLIT; q++) {
            g_degcnt[q][i] = 0;
            g_colcnt[q][i] = 0;
        }
    }
}

// ---------------------------------------------------------------------------
// K2: phase-split histograms over row (degree) and col (CSR counts)
// ---------------------------------------------------------------------------
__global__ void k_hist(const int* __restrict__ row,
                       const int* __restrict__ col, int e, int qs) {
    int i = blockIdx.x * blockDim.x + threadIdx.x;
    if (i < e) {
        int q = i / qs;                // 0..NSPLIT-1
        atomicAdd(&g_degcnt[q][row[i]], 1);
        atomicAdd(&g_colcnt[q][col[i]], 1);
    }
}

// ---------------------------------------------------------------------------
// K3: single-block scan -> CSR offsets + phase cursors; dis = rsqrt(deg+1)
// Phase sub-ranges are contiguous inside each bin => g_srow fully col-sorted.
// ---------------------------------------------------------------------------
__global__ __launch_bounds__(1024) void k_scan(int n) {
    __shared__ int sums[1024];
    const int t = threadIdx.x;
    const int chunk = (n + 1023) / 1024;
    const int beg = t * chunk;
    const int end = min(beg + chunk, n);

    int s = 0;
    for (int i = beg; i < end; i++) {
        int tot = 0;
#pragma unroll
        for (int q = 0; q < NSPLIT; q++) tot += g_colcnt[q][i];
        s += tot;
    }
    sums[t] = s;
    __syncthreads();

    for (int off = 1; off < 1024; off <<= 1) {
        int v = (t >= off) ? sums[t - off] : 0;
        __syncthreads();
        sums[t] += v;
        __syncthreads();
    }

    int run = (t == 0) ? 0 : sums[t - 1];
    for (int i = beg; i < end; i++) {
        g_off[i] = run;
        int pos = run;
#pragma unroll
        for (int q = 0; q < NSPLIT; q++) {
            g_cursor[q][i] = pos;
            pos += g_colcnt[q][i];
        }
        run = pos;
    }
    if (end == n) g_off[n] = run;

    for (int i = t; i < n; i += 1024) {
        int deg = 1;  // self loop
#pragma unroll
        for (int q = 0; q < NSPLIT; q++) deg += g_degcnt[q][i];
        g_dis[i] = rsqrtf((float)deg);
    }
}

// ---------------------------------------------------------------------------
// K4: counting-sort scatter (phase-split cursors)
// ---------------------------------------------------------------------------
__global__ void k_sort(const int* __restrict__ row,
                       const int* __restrict__ col, int e, int qs) {
    int i = blockIdx.x * blockDim.x + threadIdx.x;
    if (i < e) {
        int q = i / qs;
        int pos = atomicAdd(&g_cursor[q][col[i]], 1);
        g_srow[pos] = row[i];
    }
}

// ---------------------------------------------------------------------------
// K5: fused GEMM + row scale:  g_msg[i,:] = (x[i,:] @ W) * dis[i]
// 16 rows per 128-thread block (round-2 measured config).
// ---------------------------------------------------------------------------
#define RPB 16
__global__ __launch_bounds__(128) void k_gemm(const float* __restrict__ x,
                                              const float* __restrict__ W,
                                              int n) {
    __shared__ float4 xs[RPB][DD / 4];
    const int j  = threadIdx.x;              // output column
    const int r0 = blockIdx.x * RPB;

    const float4* x4 = (const float4*)x;
#pragma unroll
    for (int i = 0; i < RPB * (DD / 4) / 128; i++) {   // 4 float4 per thread
        int idx = j + i * 128;
        int r = idx >> 5, c = idx & 31;
        int gr = r0 + r;
        xs[r][c] = (gr < n) ? x4[gr * (DD / 4) + c]
                            : make_float4(0.f, 0.f, 0.f, 0.f);
    }
    __syncthreads();

    float acc[RPB];
#pragma unroll
    for (int r = 0; r < RPB; r++) acc[r] = 0.0f;

#pragma unroll 4
    for (int k = 0; k < DD; k += 4) {
        float w0 = W[(k + 0) * DD + j];
        float w1 = W[(k + 1) * DD + j];
        float w2 = W[(k + 2) * DD + j];
        float w3 = W[(k + 3) * DD + j];
#pragma unroll
        for (int r = 0; r < RPB; r++) {
            float4 xv = xs[r][k >> 2];
            acc[r] = fmaf(xv.x, w0, acc[r]);
            acc[r] = fmaf(xv.y, w1, acc[r]);
            acc[r] = fmaf(xv.z, w2, acc[r]);
            acc[r] = fmaf(xv.w, w3, acc[r]);
        }
    }

#pragma unroll
    for (int r = 0; r < RPB; r++) {
        int gr = r0 + r;
        if (gr < n) g_msg[gr * DD + j] = acc[r] * g_dis[gr];
    }
}

// ---------------------------------------------------------------------------
// K6: gather-reduce + finalize. One warp per node; lane l owns dims [4l,4l+4).
// out[i,:] = dis[i] * (sum_{e: col=i} g_msg[srow[e],:] + g_msg[i,:]) + bias
// 8-wide edge unroll for MLP.
// ---------------------------------------------------------------------------
__global__ __launch_bounds__(256) void k_reduce(float* __restrict__ out,
                                                const float* __restrict__ bias,
                                                int n) {
    const int node = blockIdx.x * 8 + (threadIdx.x >> 5);
    const int lane = threadIdx.x & 31;
    if (node >= n) return;

    const float4* msg4 = (const float4*)g_msg;   // row stride = 32 float4
    const int beg = g_off[node];
    const int end = g_off[node + 1];

    float4 acc = msg4[node * 32 + lane];          // self-loop term
    int e = beg;
    for (; e + 8 <= end; e += 8) {
        int r0 = g_srow[e + 0];
        int r1 = g_srow[e + 1];
        int r2 = g_srow[e + 2];
        int r3 = g_srow[e + 3];
        int r4 = g_srow[e + 4];
        int r5 = g_srow[e + 5];
        int r6 = g_srow[e + 6];
        int r7 = g_srow[e + 7];
        float4 v0 = msg4[r0 * 32 + lane];
        float4 v1 = msg4[r1 * 32 + lane];
        float4 v2 = msg4[r2 * 32 + lane];
        float4 v3 = msg4[r3 * 32 + lane];
        float4 v4 = msg4[r4 * 32 + lane];
        float4 v5 = msg4[r5 * 32 + lane];
        float4 v6 = msg4[r6 * 32 + lane];
        float4 v7 = msg4[r7 * 32 + lane];
        acc.x += ((v0.x + v1.x) + (v2.x + v3.x)) + ((v4.x + v5.x) + (v6.x + v7.x));
        acc.y += ((v0.y + v1.y) + (v2.y + v3.y)) + ((v4.y + v5.y) + (v6.y + v7.y));
        acc.z += ((v0.z + v1.z) + (v2.z + v3.z)) + ((v4.z + v5.z) + (v6.z + v7.z));
        acc.w += ((v0.w + v1.w) + (v2.w + v3.w)) + ((v4.w + v5.w) + (v6.w + v7.w));
    }
    for (; e < end; e++) {
        float4 v = msg4[g_srow[e] * 32 + lane];
        acc.x += v.x; acc.y += v.y; acc.z += v.z; acc.w += v.w;
    }

    const float s = g_dis[node];
    const float4 b = ((const float4*)bias)[lane];
    float4 o;
    o.x = fmaf(s, acc.x, b.x);
    o.y = fmaf(s, acc.y, b.y);
    o.z = fmaf(s, acc.z, b.z);
    o.w = fmaf(s, acc.w, b.w);
    ((float4*)out)[node * 32 + lane] = o;
}

// ---------------------------------------------------------------------------
extern "C" void kernel_launch(void* const* d_in, const int* in_sizes, int n_in,
                              void* d_out, int out_size) {
    const float* x    = (const float*)d_in[0];
    const int*   ei   = (const int*)d_in[1];
    const float* W    = (const float*)d_in[2];
    const float* bias = (const float*)d_in[3];
    float* out = (float*)d_out;

    const int n = in_sizes[0] / DD;   // 10000
    const int e = in_sizes[1] / 2;    // 640000
    const int qs = (e + NSPLIT - 1) / NSPLIT;

    const int* row = ei;              // edge_index[0]
    const int* col = ei + e;          // edge_index[1]

    k_zero<<<(n + 255) / 256, 256>>>(n);
    k_hist<<<(e + 255) / 256, 256>>>(row, col, e, qs);
    k_scan<<<1, 1024>>>(n);
    k_sort<<<(e + 255) / 256, 256>>>(row, col, e, qs);
    k_gemm<<<(n + RPB - 1) / RPB, 128>>>(x, W, n);
    k_reduce<<<(n + 7) / 8, 256>>>(out, bias, n);
}

// round 5
// speedup vs baseline: 1.2968x; 1.2968x over previous
#include <cuda_runtime.h>
#include <cuda_bf16.h>

#define NN 10000      // num nodes (dataset-fixed)
#define EE 640000     // num edges
#define DD 128        // feature dim
#define NSPLIT 4      // atomic contention split factor (measured best)

// ---- scratch (__device__ globals; no cudaMalloc allowed) -------------------
__device__ int   g_degcnt[NSPLIT][NN];   // out-degree counts (over row), phase-split
__device__ int   g_colcnt[NSPLIT][NN];   // in-degree counts (over col), phase-split
__device__ int   g_off[NN + 1];          // CSR offsets by col
__device__ int   g_cursor[NSPLIT][NN];   // scatter cursors, phase-split
__device__ int   g_srow[EE];             // row[] sorted by col
__device__ float g_dis[NN];              // (deg+1)^{-1/2}
__device__ float g_msg[NN * DD];         // (x@W) * dis[row], fp32

// ---------------------------------------------------------------------------
// K1: zero histograms
// ---------------------------------------------------------------------------
__global__ void k_zero(int n) {
    int i = blockIdx.x * blockDim.x + threadIdx.x;
    if (i < n) {
#pragma unroll
        for (int q = 0; q < NSPLIT; q++) {
            g_degcnt[q][i] = 0;
            g_colcnt[q][i] = 0;
        }
    }
}

// ---------------------------------------------------------------------------
// K2: phase-split histograms over row (degree) and col (CSR counts)
// ---------------------------------------------------------------------------
__global__ void k_hist(const int* __restrict__ row,
                       const int* __restrict__ col, int e, int qs) {
    int i = blockIdx.x * blockDim.x + threadIdx.x;
    if (i < e) {
        int q = i / qs;                // 0..NSPLIT-1
        atomicAdd(&g_degcnt[q][row[i]], 1);
        atomicAdd(&g_colcnt[q][col[i]], 1);
    }
}

// ---------------------------------------------------------------------------
// K3: single-block scan -> CSR offsets + phase cursors; dis = rsqrt(deg+1)
// Phase sub-ranges are contiguous inside each bin => g_srow fully col-sorted.
// ---------------------------------------------------------------------------
__global__ __launch_bounds__(1024) void k_scan(int n) {
    __shared__ int sums[1024];
    const int t = threadIdx.x;
    const int chunk = (n + 1023) / 1024;
    const int beg = t * chunk;
    const int end = min(beg + chunk, n);

    int s = 0;
    for (int i = beg; i < end; i++) {
        int tot = 0;
#pragma unroll
        for (int q = 0; q < NSPLIT; q++) tot += g_colcnt[q][i];
        s += tot;
    }
    sums[t] = s;
    __syncthreads();

    for (int off = 1; off < 1024; off <<= 1) {
        int v = (t >= off) ? sums[t - off] : 0;
        __syncthreads();
        sums[t] += v;
        __syncthreads();
    }

    int run = (t == 0) ? 0 : sums[t - 1];
    for (int i = beg; i < end; i++) {
        g_off[i] = run;
        int pos = run;
#pragma unroll
        for (int q = 0; q < NSPLIT; q++) {
            g_cursor[q][i] = pos;
            pos += g_colcnt[q][i];
        }
        run = pos;
    }
    if (end == n) g_off[n] = run;

    for (int i = t; i < n; i += 1024) {
        int deg = 1;  // self loop
#pragma unroll
        for (int q = 0; q < NSPLIT; q++) deg += g_degcnt[q][i];
        g_dis[i] = rsqrtf((float)deg);
    }
}

// ---------------------------------------------------------------------------
// K4: counting-sort scatter (phase-split cursors)
// ---------------------------------------------------------------------------
__global__ void k_sort(const int* __restrict__ row,
                       const int* __restrict__ col, int e, int qs) {
    int i = blockIdx.x * blockDim.x + threadIdx.x;
    if (i < e) {
        int q = i / qs;
        int pos = atomicAdd(&g_cursor[q][col[i]], 1);
        g_srow[pos] = row[i];
    }
}

// ---------------------------------------------------------------------------
// K5: fused GEMM + row scale:  g_msg[i,:] = (x[i,:] @ W) * dis[i]
// 16 rows per 128-thread block (round-2 measured config).
// ---------------------------------------------------------------------------
#define RPB 16
__global__ __launch_bounds__(128) void k_gemm(const float* __restrict__ x,
                                              const float* __restrict__ W,
                                              int n) {
    __shared__ float4 xs[RPB][DD / 4];
    const int j  = threadIdx.x;              // output column
    const int r0 = blockIdx.x * RPB;

    const float4* x4 = (const float4*)x;
#pragma unroll
    for (int i = 0; i < RPB * (DD / 4) / 128; i++) {   // 4 float4 per thread
        int idx = j + i * 128;
        int r = idx >> 5, c = idx & 31;
        int gr = r0 + r;
        xs[r][c] = (gr < n) ? x4[gr * (DD / 4) + c]
                            : make_float4(0.f, 0.f, 0.f, 0.f);
    }
    __syncthreads();

    float acc[RPB];
#pragma unroll
    for (int r = 0; r < RPB; r++) acc[r] = 0.0f;

#pragma unroll 4
    for (int k = 0; k < DD; k += 4) {
        float w0 = W[(k + 0) * DD + j];
        float w1 = W[(k + 1) * DD + j];
        float w2 = W[(k + 2) * DD + j];
        float w3 = W[(k + 3) * DD + j];
#pragma unroll
        for (int r = 0; r < RPB; r++) {
            float4 xv = xs[r][k >> 2];
            acc[r] = fmaf(xv.x, w0, acc[r]);
            acc[r] = fmaf(xv.y, w1, acc[r]);
            acc[r] = fmaf(xv.z, w2, acc[r]);
            acc[r] = fmaf(xv.w, w3, acc[r]);
        }
    }

#pragma unroll
    for (int r = 0; r < RPB; r++) {
        int gr = r0 + r;
        if (gr < n) g_msg[gr * DD + j] = acc[r] * g_dis[gr];
    }
}

// ---------------------------------------------------------------------------
// K6: gather-reduce + finalize (exact round-2 version: unroll 4, fp32).
// One warp per node; lane l owns dims [4l,4l+4).
// out[i,:] = dis[i] * (sum_{e: col=i} g_msg[srow[e],:] + g_msg[i,:]) + bias
// ---------------------------------------------------------------------------
__global__ __launch_bounds__(256) void k_reduce(float* __restrict__ out,
                                                const float* __restrict__ bias,
                                                int n) {
    const int node = blockIdx.x * 8 + (threadIdx.x >> 5);
    const int lane = threadIdx.x & 31;
    if (node >= n) return;

    const float4* msg4 = (const float4*)g_msg;   // row stride = 32 float4
    const int beg = g_off[node];
    const int end = g_off[node + 1];

    float4 acc = msg4[node * 32 + lane];          // self-loop term
    int e = beg;
    for (; e + 4 <= end; e += 4) {
        int r0 = g_srow[e + 0];
        int r1 = g_srow[e + 1];
        int r2 = g_srow[e + 2];
        int r3 = g_srow[e + 3];
        float4 v0 = msg4[r0 * 32 + lane];
        float4 v1 = msg4[r1 * 32 + lane];
        float4 v2 = msg4[r2 * 32 + lane];
        float4 v3 = msg4[r3 * 32 + lane];
        acc.x += (v0.x + v1.x) + (v2.x + v3.x);
        acc.y += (v0.y + v1.y) + (v2.y + v3.y);
        acc.z += (v0.z + v1.z) + (v2.z + v3.z);
        acc.w += (v0.w + v1.w) + (v2.w + v3.w);
    }
    for (; e < end; e++) {
        float4 v = msg4[g_srow[e] * 32 + lane];
        acc.x += v.x; acc.y += v.y; acc.z += v.z; acc.w += v.w;
    }

    const float s = g_dis[node];
    const float4 b = ((const float4*)bias)[lane];
    float4 o;
    o.x = fmaf(s, acc.x, b.x);
    o.y = fmaf(s, acc.y, b.y);
    o.z = fmaf(s, acc.z, b.z);
    o.w = fmaf(s, acc.w, b.w);
    ((float4*)out)[node * 32 + lane] = o;
}

// ---------------------------------------------------------------------------
extern "C" void kernel_launch(void* const* d_in, const int* in_sizes, int n_in,
                              void* d_out, int out_size) {
    const float* x    = (const float*)d_in[0];
    const int*   ei   = (const int*)d_in[1];
    const float* W    = (const float*)d_in[2];
    const float* bias = (const float*)d_in[3];
    float* out = (float*)d_out;

    const int n = in_sizes[0] / DD;   // 10000
    const int e = in_sizes[1] / 2;    // 640000
    const int qs = (e + NSPLIT - 1) / NSPLIT;

    const int* row = ei;              // edge_index[0]
    const int* col = ei + e;          // edge_index[1]

    k_zero<<<(n + 255) / 256, 256>>>(n);
    k_hist<<<(e + 255) / 256, 256>>>(row, col, e, qs);
    k_scan<<<1, 1024>>>(n);
    k_sort<<<(e + 255) / 256, 256>>>(row, col, e, qs);
    k_gemm<<<(n + RPB - 1) / RPB, 128>>>(x, W, n);
    k_reduce<<<(n + 7) / 8, 256>>>(out, bias, n);
}

// round 6
// speedup vs baseline: 1.5234x; 1.1747x over previous
#include <cuda_runtime.h>
#include <cuda_bf16.h>

#define NN 10000      // num nodes (dataset-fixed)
#define EE 640000     // num edges
#define DD 128        // feature dim

// ---- scratch (__device__ globals; zero-initialized at load) ----------------
__device__ int   g_degcnt[NN];       // out-degree counts (over row)
__device__ int   g_colcnt[NN];       // in-degree counts (over col)
__device__ int   g_off[NN + 1];      // CSR offsets by col
__device__ int   g_cursor[NN];       // scatter cursors
__device__ int   g_srow[EE];         // row[] sorted by col
__device__ float g_dis[NN];          // (deg+1)^{-1/2}
__device__ float g_msg[NN * DD];     // (x@W) * dis[row], fp32

// NOTE: g_degcnt/g_colcnt must be ZERO on entry. They are zero at module load,
// and k_reduce's tail blocks re-zero them at the end of every call, so each
// graph replay starts from a clean state. No separate zeroing launch needed.

// ---------------------------------------------------------------------------
// K1: histograms over row (degree) and col (CSR counts). ILP-2: each thread
// handles edges i and i+half, keeping 4 independent atomics in flight.
// ---------------------------------------------------------------------------
__global__ void k_hist(const int* __restrict__ row,
                       const int* __restrict__ col, int e, int half) {
    int i = blockIdx.x * blockDim.x + threadIdx.x;
    if (i < half) {
        int r0 = row[i];
        int c0 = col[i];
        int j = i + half;
        if (j < e) {
            int r1 = row[j];
            int c1 = col[j];
            atomicAdd(&g_degcnt[r0], 1);
            atomicAdd(&g_degcnt[r1], 1);
            atomicAdd(&g_colcnt[c0], 1);
            atomicAdd(&g_colcnt[c1], 1);
        } else {
            atomicAdd(&g_degcnt[r0], 1);
            atomicAdd(&g_colcnt[c0], 1);
        }
    }
}

// ---------------------------------------------------------------------------
// K2: single-block exclusive scan of colcnt -> offsets/cursor; dis = rsqrt(deg+1)
// (byte-identical logic to the 86.8us round-2 version)
// ---------------------------------------------------------------------------
__global__ __launch_bounds__(1024) void k_scan(int n) {
    __shared__ int sums[1024];
    const int t = threadIdx.x;
    const int chunk = (n + 1023) / 1024;
    const int beg = t * chunk;
    const int end = min(beg + chunk, n);

    int s = 0;
    for (int i = beg; i < end; i++) s += g_colcnt[i];
    sums[t] = s;
    __syncthreads();

    for (int off = 1; off < 1024; off <<= 1) {
        int v = (t >= off) ? sums[t - off] : 0;
        __syncthreads();
        sums[t] += v;
        __syncthreads();
    }

    int run = (t == 0) ? 0 : sums[t - 1];
    for (int i = beg; i < end; i++) {
        g_off[i]    = run;
        g_cursor[i] = run;
        run += g_colcnt[i];
    }
    if (end == n && beg <= n) g_off[n] = run;

    for (int i = t; i < n; i += 1024)
        g_dis[i] = rsqrtf((float)(g_degcnt[i] + 1));  // +1 self-loop
}

// ---------------------------------------------------------------------------
// K3: counting-sort scatter. ILP-2: two independent atomic+store chains.
// ---------------------------------------------------------------------------
__global__ void k_sort(const int* __restrict__ row,
                       const int* __restrict__ col, int e, int half) {
    int i = blockIdx.x * blockDim.x + threadIdx.x;
    if (i < half) {
        int c0 = col[i];
        int r0 = row[i];
        int j = i + half;
        if (j < e) {
            int c1 = col[j];
            int r1 = row[j];
            int p0 = atomicAdd(&g_cursor[c0], 1);
            int p1 = atomicAdd(&g_cursor[c1], 1);
            g_srow[p0] = r0;
            g_srow[p1] = r1;
        } else {
            int p0 = atomicAdd(&g_cursor[c0], 1);
            g_srow[p0] = r0;
        }
    }
}

// ---------------------------------------------------------------------------
// K4: fused GEMM + row scale:  g_msg[i,:] = (x[i,:] @ W) * dis[i]
// 16 rows per 128-thread block (round-2 measured config, unchanged).
// ---------------------------------------------------------------------------
#define RPB 16
__global__ __launch_bounds__(128) void k_gemm(const float* __restrict__ x,
                                              const float* __restrict__ W,
                                              int n) {
    __shared__ float4 xs[RPB][DD / 4];
    const int j  = threadIdx.x;              // output column
    const int r0 = blockIdx.x * RPB;

    const float4* x4 = (const float4*)x;
#pragma unroll
    for (int i = 0; i < RPB * (DD / 4) / 128; i++) {   // 4 float4 per thread
        int idx = j + i * 128;
        int r = idx >> 5, c = idx & 31;
        int gr = r0 + r;
        xs[r][c] = (gr < n) ? x4[gr * (DD / 4) + c]
                            : make_float4(0.f, 0.f, 0.f, 0.f);
    }
    __syncthreads();

    float acc[RPB];
#pragma unroll
    for (int r = 0; r < RPB; r++) acc[r] = 0.0f;

#pragma unroll 4
    for (int k = 0; k < DD; k += 4) {
        float w0 = W[(k + 0) * DD + j];
        float w1 = W[(k + 1) * DD + j];
        float w2 = W[(k + 2) * DD + j];
        float w3 = W[(k + 3) * DD + j];
#pragma unroll
        for (int r = 0; r < RPB; r++) {
            float4 xv = xs[r][k >> 2];
            acc[r] = fmaf(xv.x, w0, acc[r]);
            acc[r] = fmaf(xv.y, w1, acc[r]);
            acc[r] = fmaf(xv.z, w2, acc[r]);
            acc[r] = fmaf(xv.w, w3, acc[r]);
        }
    }

#pragma unroll
    for (int r = 0; r < RPB; r++) {
        int gr = r0 + r;
        if (gr < n) g_msg[gr * DD + j] = acc[r] * g_dis[gr];
    }
}

// ---------------------------------------------------------------------------
// K5: gather-reduce + finalize (round-2 version: unroll 4, fp32), plus tail
// blocks that zero the histogram counters for the next call.
// One warp per node; lane l owns dims [4l,4l+4).
// ---------------------------------------------------------------------------
#define NODE_BLOCKS ((NN + 7) / 8)
#define ZERO_BLOCKS 8
__global__ __launch_bounds__(256) void k_reduce(float* __restrict__ out,
                                                const float* __restrict__ bias,
                                                int n) {
    if (blockIdx.x >= NODE_BLOCKS) {
        // counter cleanup for the next call (runs after hist/scan consumed them)
        int t = (blockIdx.x - NODE_BLOCKS) * 256 + threadIdx.x;
        int stride = ZERO_BLOCKS * 256;
        for (int i = t; i < NN; i += stride) {
            g_degcnt[i] = 0;
            g_colcnt[i] = 0;
        }
        return;
    }

    const int node = blockIdx.x * 8 + (threadIdx.x >> 5);
    const int lane = threadIdx.x & 31;
    if (node >= n) return;

    const float4* msg4 = (const float4*)g_msg;   // row stride = 32 float4
    const int beg = g_off[node];
    const int end = g_off[node + 1];

    float4 acc = msg4[node * 32 + lane];          // self-loop term
    int e = beg;
    for (; e + 4 <= end; e += 4) {
        int r0 = g_srow[e + 0];
        int r1 = g_srow[e + 1];
        int r2 = g_srow[e + 2];
        int r3 = g_srow[e + 3];
        float4 v0 = msg4[r0 * 32 + lane];
        float4 v1 = msg4[r1 * 32 + lane];
        float4 v2 = msg4[r2 * 32 + lane];
        float4 v3 = msg4[r3 * 32 + lane];
        acc.x += (v0.x + v1.x) + (v2.x + v3.x);
        acc.y += (v0.y + v1.y) + (v2.y + v3.y);
        acc.z += (v0.z + v1.z) + (v2.z + v3.z);
        acc.w += (v0.w + v1.w) + (v2.w + v3.w);
    }
    for (; e < end; e++) {
        float4 v = msg4[g_srow[e] * 32 + lane];
        acc.x += v.x; acc.y += v.y; acc.z += v.z; acc.w += v.w;
    }

    const float s = g_dis[node];
    const float4 b = ((const float4*)bias)[lane];
    float4 o;
    o.x = fmaf(s, acc.x, b.x);
    o.y = fmaf(s, acc.y, b.y);
    o.z = fmaf(s, acc.z, b.z);
    o.w = fmaf(s, acc.w, b.w);
    ((float4*)out)[node * 32 + lane] = o;
}

// ---------------------------------------------------------------------------
extern "C" void kernel_launch(void* const* d_in, const int* in_sizes, int n_in,
                              void* d_out, int out_size) {
    const float* x    = (const float*)d_in[0];
    const int*   ei   = (const int*)d_in[1];
    const float* W    = (const float*)d_in[2];
    const float* bias = (const float*)d_in[3];
    float* out = (float*)d_out;

    const int n = in_sizes[0] / DD;   // 10000
    const int e = in_sizes[1] / 2;    // 640000
    const int half = (e + 1) / 2;

    const int* row = ei;              // edge_index[0]
    const int* col = ei + e;          // edge_index[1]

    k_hist<<<(half + 255) / 256, 256>>>(row, col, e, half);
    k_scan<<<1, 1024>>>(n);
    k_sort<<<(half + 255) / 256, 256>>>(row, col, e, half);
    k_gemm<<<(n + RPB - 1) / RPB, 128>>>(x, W, n);
    k_reduce<<<NODE_BLOCKS + ZERO_BLOCKS, 256>>>(out, bias, n);
}